// round 16
// baseline (speedup 1.0000x reference)
#include <cuda_runtime.h>
#include <cuda_fp16.h>
#include <cstdint>

#define NNODES   100000
#define MAXDEG   16
#define DIM      128
#define HIDDEN   256
#define NBLOCKS  5
#define NGRAPHS  2048
#define CATW     (DIM * (NBLOCKS + 1))   // 768
#define BN_EPS   1e-5f
#define RPB      49
#define SEGBLK   ((NNODES + RPB - 1) / RPB)   // 2041

// ---------------- scratch ----------------
__device__ float    d_h[(size_t)NNODES * DIM];
__device__ float    d_aggr[(size_t)NNODES * 2 * DIM];
__device__ float    d_zA[(size_t)NNODES * DIM];
__device__ float    d_tB[(size_t)NNODES * HIDDEN];
__device__ unsigned d_cminu[DIM];
__device__ float    d_stats[2 * DIM];
__device__ float    d_g[(size_t)NGRAPHS * CATW];
__device__ float    d_g1[(size_t)NGRAPHS * HIDDEN];
__device__ float    d_g2[(size_t)NGRAPHS * DIM];
__device__ __half   d_wthi[15 * 32768];
__device__ __half   d_wtlo[15 * 32768];

// ---------------- helpers ----------------
#define FMA2(d, a, b, c) \
    asm("fma.rn.f32x2 %0, %1, %2, %3;" : "=l"(d) : "l"(a), "l"(b), "l"(c))
#define PACK2(d, x) \
    asm("mov.b64 %0, {%1, %1};" : "=l"(d) : "f"(x))

__device__ __forceinline__ unsigned f2o(float f) {
    unsigned u = __float_as_uint(f);
    return (u & 0x80000000u) ? ~u : (u | 0x80000000u);
}
__device__ __forceinline__ float o2f(unsigned o) {
    unsigned u = (o & 0x80000000u) ? (o & 0x7FFFFFFFu) : ~o;
    return __uint_as_float(u);
}
__device__ __forceinline__ uint32_t s2u(const void* p) {
    uint32_t a;
    asm("{ .reg .u64 t; cvta.to.shared.u64 t, %1; cvt.u32.u64 %0, t; }"
        : "=r"(a) : "l"(p));
    return a;
}

#define LDSM_X4(r0, r1, r2, r3, addr) \
    asm volatile("ldmatrix.sync.aligned.m8n8.x4.shared.b16 {%0,%1,%2,%3}, [%4];" \
        : "=r"(r0), "=r"(r1), "=r"(r2), "=r"(r3) : "r"(addr))
#define LDSM_X4T(r0, r1, r2, r3, addr) \
    asm volatile("ldmatrix.sync.aligned.m8n8.x4.trans.shared.b16 {%0,%1,%2,%3}, [%4];" \
        : "=r"(r0), "=r"(r1), "=r"(r2), "=r"(r3) : "r"(addr))
#define MMA16816(c, a, b0, b1) \
    asm volatile("mma.sync.aligned.m16n8k16.row.col.f32.f16.f16.f32 " \
        "{%0,%1,%2,%3}, {%4,%5,%6,%7}, {%8,%9}, {%0,%1,%2,%3};" \
        : "+f"((c)[0]), "+f"((c)[1]), "+f"((c)[2]), "+f"((c)[3]) \
        : "r"((a)[0]), "r"((a)[1]), "r"((a)[2]), "r"((a)[3]), "r"(b0), "r"(b1))
#define CP16(dst, src) \
    asm volatile("cp.async.cg.shared.global [%0], [%1], 16;" :: "r"(dst), "l"(src))
#define CP_COMMIT() asm volatile("cp.async.commit_group;")
#define CP_WAIT(n)  asm volatile("cp.async.wait_group %0;" :: "n"(n))

#define OFF_AL 10240
#define OFF_BH 20480
#define BUFSZ  37888
#define ZCH    20480
#define P2B    81920
#define SMEM_FUSED (P2B + 17408)   // 99328

// ---------------- small utility kernels ----------------
__global__ void fill_u32_kernel(unsigned* p, unsigned v, int n) {
    int i = blockIdx.x * blockDim.x + threadIdx.x;
    if (i < n) p[i] = v;
}

__global__ void reset_kernel(float* stats, unsigned* cmin) {
    int t = threadIdx.x;
    if (t < 256) stats[t] = 0.f;
    else cmin[t - 256] = 0xFFFFFFFFu;
}

// h = x; colmin(x); segment-sum x into G[:,0:128]   (2-row unrolled, 128 thr)
__global__ void init_kernel(const float* __restrict__ x,
                            float* __restrict__ h,
                            const int* __restrict__ mem,
                            float* __restrict__ G,
                            unsigned* __restrict__ cmin) {
    int r0 = blockIdx.x * RPB;
    if (r0 >= NNODES) return;
    int r1 = min(r0 + RPB, NNODES);
    int c = threadIdx.x;
    unsigned best = 0xFFFFFFFFu;
    int curg = mem[r0];
    float acc = 0.f;
    int r = r0;
    for (; r + 1 < r1; r += 2) {
        size_t o0 = (size_t)r * DIM + c, o1 = o0 + DIM;
        float v0 = x[o0];
        float v1 = x[o1];
        int g0 = mem[r], g1 = mem[r + 1];
        h[o0] = v0;
        h[o1] = v1;
        best = min(best, min(f2o(v0), f2o(v1)));
        if (g0 != curg) {
            atomicAdd(&G[(size_t)curg * CATW + c], acc);
            acc = 0.f; curg = g0;
        }
        acc += v0;
        if (g1 != curg) {
            atomicAdd(&G[(size_t)curg * CATW + c], acc);
            acc = 0.f; curg = g1;
        }
        acc += v1;
    }
    if (r < r1) {
        size_t o = (size_t)r * DIM + c;
        float v = x[o];
        h[o] = v;
        best = min(best, f2o(v));
        int g = mem[r];
        if (g != curg) {
            atomicAdd(&G[(size_t)curg * CATW + c], acc);
            acc = 0.f; curg = g;
        }
        acc += v;
    }
    atomicAdd(&G[(size_t)curg * CATW + c], acc);
    atomicMin(&cmin[c], best);
}

__global__ void wsplit_kernel(const float* __restrict__ mW,
                              const float* __restrict__ l1W,
                              const float* __restrict__ l2W,
                              __half* __restrict__ whi, __half* __restrict__ wlo) {
    int i = blockIdx.x * 256 + threadIdx.x;
    if (i >= 15 * 32768) return;
    int slot = i >> 15;
    int e = i & 32767;
    int b = slot / 3, m = slot - 3 * b;
    const float* W = (m == 0) ? mW + (size_t)b * 32768
                   : (m == 1) ? l1W + (size_t)b * 32768
                              : l2W + (size_t)b * 32768;
    float w = W[e];
    __half hi = __float2half_rn(w);
    __half lo = __float2half_rn(w - __half2float(hi));
    whi[i] = hi;
    wlo[i] = lo;
}

__global__ void colstats_kernel(const float* __restrict__ X, int M,
                                float* __restrict__ stats) {
    int c = threadIdx.x;
    float s = 0.f, s2 = 0.f;
    for (int r = blockIdx.x; r < M; r += gridDim.x) {
        float v = X[(size_t)r * DIM + c];
        s += v; s2 += v * v;
    }
    atomicAdd(&stats[c], s);
    atomicAdd(&stats[DIM + c], s2);
}

// fused sum+max aggregation; 2 nodes per warp; packed 16B split stores.
__global__ void aggregate_kernel(const float* __restrict__ H,
                                 const int* __restrict__ nbrs,
                                 const unsigned* __restrict__ cminu,
                                 __half* __restrict__ aHi,
                                 __half* __restrict__ aLo) {
    int warp = threadIdx.x >> 5;
    int lane = threadIdx.x & 31;
    int node0 = blockIdx.x * 16 + warp * 2;
    int node1 = node0 + 1;
    if (node0 >= NNODES) return;
    bool has1 = (node1 < NNODES);

    float4 mm[2], ss[2];
    mm[0].x = o2f(cminu[lane * 4 + 0]);
    mm[0].y = o2f(cminu[lane * 4 + 1]);
    mm[0].z = o2f(cminu[lane * 4 + 2]);
    mm[0].w = o2f(cminu[lane * 4 + 3]);
    mm[1] = mm[0];
    ss[0] = make_float4(0.f, 0.f, 0.f, 0.f);
    ss[1] = ss[0];

    int idx0[MAXDEG], idx1[MAXDEG];
    const int* nb0 = nbrs + (size_t)node0 * MAXDEG;
    const int* nb1 = nbrs + (size_t)(has1 ? node1 : node0) * MAXDEG;
#pragma unroll
    for (int j = 0; j < MAXDEG; j++) idx0[j] = __ldg(&nb0[j]);
#pragma unroll
    for (int j = 0; j < MAXDEG; j++) idx1[j] = __ldg(&nb1[j]);

    const float4* H4 = (const float4*)H;
#pragma unroll
    for (int g = 0; g < 2; g++) {
        float4 v0[8], v1[8];
#pragma unroll
        for (int j = 0; j < 8; j++) {
            int n = idx0[g * 8 + j];
            v0[j] = H4[(size_t)(n >= 0 ? n : node0) * 32 + lane];
        }
#pragma unroll
        for (int j = 0; j < 8; j++) {
            int n = idx1[g * 8 + j];
            v1[j] = H4[(size_t)(n >= 0 ? n : node0) * 32 + lane];
        }
#pragma unroll
        for (int j = 0; j < 8; j++) {
            if (idx0[g * 8 + j] >= 0) {
                float4 v = v0[j];
                ss[0].x += v.x; ss[0].y += v.y; ss[0].z += v.z; ss[0].w += v.w;
                mm[0].x = fmaxf(mm[0].x, v.x); mm[0].y = fmaxf(mm[0].y, v.y);
                mm[0].z = fmaxf(mm[0].z, v.z); mm[0].w = fmaxf(mm[0].w, v.w);
            }
        }
#pragma unroll
        for (int j = 0; j < 8; j++) {
            if (idx1[g * 8 + j] >= 0) {
                float4 v = v1[j];
                ss[1].x += v.x; ss[1].y += v.y; ss[1].z += v.z; ss[1].w += v.w;
                mm[1].x = fmaxf(mm[1].x, v.x); mm[1].y = fmaxf(mm[1].y, v.y);
                mm[1].z = fmaxf(mm[1].z, v.z); mm[1].w = fmaxf(mm[1].w, v.w);
            }
        }
    }

#pragma unroll
    for (int nn = 0; nn < 2; nn++) {
        if (nn == 1 && !has1) break;
        int node = node0 + nn;
        float sv[8] = {ss[nn].x, ss[nn].y, ss[nn].z, ss[nn].w,
                       mm[nn].x, mm[nn].y, mm[nn].z, mm[nn].w};
#pragma unroll
        for (int q = 0; q < 2; q++) {
            __half h0 = __float2half_rn(sv[q * 4 + 0]);
            __half h1 = __float2half_rn(sv[q * 4 + 1]);
            __half h2 = __float2half_rn(sv[q * 4 + 2]);
            __half h3 = __float2half_rn(sv[q * 4 + 3]);
            __half l0 = __float2half_rn(sv[q * 4 + 0] - __half2float(h0));
            __half l1 = __float2half_rn(sv[q * 4 + 1] - __half2float(h1));
            __half l2 = __float2half_rn(sv[q * 4 + 2] - __half2float(h2));
            __half l3 = __float2half_rn(sv[q * 4 + 3] - __half2float(h3));
            size_t off = (size_t)node * 256 + q * 128 + lane * 4;
            uint2 ph, pl;
            __half2 t0 = __halves2half2(h0, h1), t1 = __halves2half2(h2, h3);
            ph.x = *(uint32_t*)&t0; ph.y = *(uint32_t*)&t1;
            __half2 t2 = __halves2half2(l0, l1), t3 = __halves2half2(l2, l3);
            pl.x = *(uint32_t*)&t2; pl.y = *(uint32_t*)&t3;
            *(uint2*)&aHi[off] = ph;
            *(uint2*)&aLo[off] = pl;
        }
    }
}

// ============ shared GEMM building blocks ====================================
__device__ __forceinline__ void fillB(uint32_t bufBH, const __half* Bh,
                                      const __half* Bl, int k0, int Nfull,
                                      int nBase, int tid) {
#pragma unroll
    for (int i = 0; i < 2; i++) {
        int idx = tid + 256 * i;
        int k = idx >> 4, c = idx & 15;
        uint32_t d = k * 272 + c * 16;
        size_t srcOff = (size_t)(k0 + k) * Nfull + nBase + c * 8;
        CP16(bufBH + d, Bh + srcOff);
        CP16(bufBH + 8704 + d, Bl + srcOff);
    }
}

template <bool FULL>
__device__ __forceinline__ void fillA(uint32_t buf, const __half* Ahi,
                                      const __half* Alo, int M, int K,
                                      int rowBase, int k0, int tid) {
#pragma unroll
    for (int i = 0; i < 2; i++) {
        int idx = tid + 256 * i;
        int r = idx >> 2, c16 = idx & 3;
        if (FULL || rowBase + r < M) {
            size_t srcOff = (size_t)(rowBase + r) * K + k0 + c16 * 8;
            uint32_t d = r * 80 + c16 * 16;
            CP16(buf + d, Ahi + srcOff);
            CP16(buf + OFF_AL + d, Alo + srcOff);
        }
    }
}

// 32 K-cols of 3-product MMA, fp32 accumulate
__device__ __forceinline__ void mma_chunk(uint32_t abuf, uint32_t bbuf,
                                          int lane, int wm, int wn,
                                          float (&acc)[2][8][4]) {
    const int lr = lane & 15, lc = lane >> 4;
#pragma unroll
    for (int ks = 0; ks < 2; ks++) {
        uint32_t ah[2][4], al[2][4];
#pragma unroll
        for (int im = 0; im < 2; im++) {
            uint32_t aoff = (uint32_t)(wm * 32 + im * 16 + lr) * 80 + ks * 32 + lc * 16;
            LDSM_X4(ah[im][0], ah[im][1], ah[im][2], ah[im][3], abuf + aoff);
            LDSM_X4(al[im][0], al[im][1], al[im][2], al[im][3], abuf + OFF_AL + aoff);
        }
        uint32_t boff = (uint32_t)(ks * 16 + lr) * 272 + lc * 16 + wn * 128;
#pragma unroll
        for (int ng = 0; ng < 4; ng++) {
            uint32_t bh0, bh1, bh2, bh3;
            LDSM_X4T(bh0, bh1, bh2, bh3, bbuf + boff + ng * 32);
#pragma unroll
            for (int im = 0; im < 2; im++) {
                MMA16816(acc[im][ng * 2 + 0], ah[im], bh0, bh1);
                MMA16816(acc[im][ng * 2 + 1], ah[im], bh2, bh3);
            }
#pragma unroll
            for (int im = 0; im < 2; im++) {
                MMA16816(acc[im][ng * 2 + 0], al[im], bh0, bh1);
                MMA16816(acc[im][ng * 2 + 1], al[im], bh2, bh3);
            }
            uint32_t bl0, bl1, bl2, bl3;
            LDSM_X4T(bl0, bl1, bl2, bl3, bbuf + 8704 + boff + ng * 32);
#pragma unroll
            for (int im = 0; im < 2; im++) {
                MMA16816(acc[im][ng * 2 + 0], ah[im], bl0, bl1);
                MMA16816(acc[im][ng * 2 + 1], ah[im], bl2, bl3);
            }
        }
    }
}

// ============ fused GEMM1+GEMM2 ==============================================
__global__ __launch_bounds__(256, 2)
void fused_gemm12_kernel(const __half* __restrict__ Ahi, const __half* __restrict__ Alo,
                         const __half* __restrict__ W0h, const __half* __restrict__ W0l,
                         const float* __restrict__ b0v,
                         const __half* __restrict__ W1h, const __half* __restrict__ W1l,
                         const float* __restrict__ b1v,
                         __half* __restrict__ tHi, __half* __restrict__ tLo,
                         int M, const float* __restrict__ hsrc,
                         const float* __restrict__ epsv, int blk,
                         float* __restrict__ statsReset) {
    extern __shared__ char smem[];
    const uint32_t sb = s2u(smem);
    const int tid = threadIdx.x;
    const int lane = tid & 31, wid = tid >> 5;
    const int wm = wid >> 1, wn = wid & 1;
    const int rowBase = blockIdx.x * 128;
    const bool full = (rowBase + 128 <= M);
    const int r0l = lane >> 2, c0l = (lane & 3) * 2;

    if (blockIdx.x == 0 && statsReset) statsReset[tid] = 0.f;

    float acc[2][8][4];
#pragma unroll
    for (int i = 0; i < 2; i++)
#pragma unroll
        for (int j = 0; j < 8; j++)
#pragma unroll
            for (int k = 0; k < 4; k++) acc[i][j][k] = 0.f;

    if (full) fillA<true>(sb, Ahi, Alo, M, 256, rowBase, 0, tid);
    else      fillA<false>(sb, Ahi, Alo, M, 256, rowBase, 0, tid);
    fillB(sb + OFF_BH, W0h, W0l, 0, 128, 0, tid);
    CP_COMMIT();

    for (int c = 0; c < 8; c++) {
        int b = c & 1;
        if (c + 1 < 8) {
            uint32_t nb = sb + (b ^ 1) * BUFSZ;
            if (full) fillA<true>(nb, Ahi, Alo, M, 256, rowBase, (c + 1) * 32, tid);
            else      fillA<false>(nb, Ahi, Alo, M, 256, rowBase, (c + 1) * 32, tid);
            fillB(nb + OFF_BH, W0h, W0l, (c + 1) * 32, 128, 0, tid);
            CP_COMMIT();
            CP_WAIT(1);
        } else {
            CP_WAIT(0);
        }
        __syncthreads();
        mma_chunk(sb + b * BUFSZ, sb + b * BUFSZ + OFF_BH, lane, wm, wn, acc);
        __syncthreads();
    }

    // prefetch first phase-2 W1 chunk
    fillB(sb + P2B, W1h, W1l, 0, 256, 0, tid);
    CP_COMMIT();

    {
        float scale = 1.0f + epsv[blk];
#pragma unroll
        for (int im = 0; im < 2; im++) {
#pragma unroll
            for (int jn = 0; jn < 8; jn++) {
                int cloc = wn * 64 + jn * 8 + c0l;
                float bv0 = b0v[cloc], bv1 = b0v[cloc + 1];
                int kc = cloc >> 5, cc = cloc & 31;
#pragma unroll
                for (int hf = 0; hf < 2; hf++) {
                    int rloc = wm * 32 + im * 16 + r0l + hf * 8;
                    int row = rowBase + rloc;
                    if (full || row < M) {
                        float v0 = acc[im][jn][hf * 2 + 0] + bv0 +
                                   scale * hsrc[(size_t)row * DIM + cloc];
                        float v1 = acc[im][jn][hf * 2 + 1] + bv1 +
                                   scale * hsrc[(size_t)row * DIM + cloc + 1];
                        __half h0 = __float2half_rn(v0), h1 = __float2half_rn(v1);
                        __half l0 = __float2half_rn(v0 - __half2float(h0));
                        __half l1 = __float2half_rn(v1 - __half2float(h1));
                        char* zp = smem + kc * ZCH + rloc * 80 + cc * 2;
                        *(__half2*)(zp)         = __halves2half2(h0, h1);
                        *(__half2*)(zp + 10240) = __halves2half2(l0, l1);
                    }
                }
            }
        }
    }
    __syncthreads();

#pragma unroll
    for (int nh = 0; nh < 2; nh++) {
        float a2[2][8][4];
#pragma unroll
        for (int i = 0; i < 2; i++)
#pragma unroll
            for (int j = 0; j < 8; j++)
#pragma unroll
                for (int k = 0; k < 4; k++) a2[i][j][k] = 0.f;

        for (int kc = 0; kc < 4; kc++) {
            CP_WAIT(0);
            __syncthreads();
            mma_chunk(sb + kc * ZCH, sb + P2B, lane, wm, wn, a2);
            __syncthreads();
            int it = nh * 4 + kc;
            if (it < 7) {
                int nit = it + 1, nnh = nit >> 2, nkc = nit & 3;
                fillB(sb + P2B, W1h, W1l, nkc * 32, 256, nnh * 128, tid);
                CP_COMMIT();
            }
        }

#pragma unroll
        for (int im = 0; im < 2; im++) {
#pragma unroll
            for (int jn = 0; jn < 8; jn++) {
                int col = nh * 128 + wn * 64 + jn * 8 + c0l;
                float bv0 = b1v[col], bv1 = b1v[col + 1];
#pragma unroll
                for (int hf = 0; hf < 2; hf++) {
                    int row = rowBase + wm * 32 + im * 16 + r0l + hf * 8;
                    if (full || row < M) {
                        float v0 = fmaxf(a2[im][jn][hf * 2 + 0] + bv0, 0.f);
                        float v1 = fmaxf(a2[im][jn][hf * 2 + 1] + bv1, 0.f);
                        __half h0 = __float2half_rn(v0), h1 = __float2half_rn(v1);
                        __half l0 = __float2half_rn(v0 - __half2float(h0));
                        __half l1 = __float2half_rn(v1 - __half2float(h1));
                        size_t o = (size_t)row * HIDDEN + col;
                        *(__half2*)&tHi[o] = __halves2half2(h0, h1);
                        *(__half2*)&tLo[o] = __halves2half2(l0, l1);
                    }
                }
            }
        }
    }
}

// ============ standalone HMMA GEMM (GEMM3) ==================================
__global__ __launch_bounds__(256, 2)
void hmma_gemm_kernel(const __half* __restrict__ Ahi, const __half* __restrict__ Alo,
                      const __half* __restrict__ Bh, const __half* __restrict__ Bl,
                      const float* __restrict__ bias,
                      __half* __restrict__ Chi, __half* __restrict__ Clo,
                      int M, int K, int Nfull,
                      float* __restrict__ statsOut,
                      unsigned* __restrict__ cminReset) {
    extern __shared__ char smem[];
    const uint32_t sb = s2u(smem);
    const int tid = threadIdx.x;
    const int lane = tid & 31, wid = tid >> 5;
    const int wm = wid >> 1, wn = wid & 1;
    const int rowBase = blockIdx.x * 128;
    const int nBase   = blockIdx.y * 128;
    const int NC = K >> 5;
    const bool full = (rowBase + 128 <= M);

    if (blockIdx.x == 0 && blockIdx.y == 0) {
        if (cminReset && tid < 128) cminReset[tid] = 0xFFFFFFFFu;
    }

    float acc[2][8][4];
#pragma unroll
    for (int i = 0; i < 2; i++)
#pragma unroll
        for (int j = 0; j < 8; j++)
#pragma unroll
            for (int k = 0; k < 4; k++) acc[i][j][k] = 0.f;

    if (full) fillA<true>(sb, Ahi, Alo, M, K, rowBase, 0, tid);
    else      fillA<false>(sb, Ahi, Alo, M, K, rowBase, 0, tid);
    fillB(sb + OFF_BH, Bh, Bl, 0, Nfull, nBase, tid);
    CP_COMMIT();

    for (int c = 0; c < NC; c++) {
        int b = c & 1;
        if (c + 1 < NC) {
            uint32_t nb = sb + (b ^ 1) * BUFSZ;
            if (full) fillA<true>(nb, Ahi, Alo, M, K, rowBase, (c + 1) * 32, tid);
            else      fillA<false>(nb, Ahi, Alo, M, K, rowBase, (c + 1) * 32, tid);
            fillB(nb + OFF_BH, Bh, Bl, (c + 1) * 32, Nfull, nBase, tid);
            CP_COMMIT();
            CP_WAIT(1);
        } else {
            CP_WAIT(0);
        }
        __syncthreads();
        mma_chunk(sb + b * BUFSZ, sb + b * BUFSZ + OFF_BH, lane, wm, wn, acc);
        __syncthreads();
    }

    float* ssum = (float*)smem;
    float* ssq  = ssum + 128;
    if (statsOut) {
        if (tid < 128) { ssum[tid] = 0.f; ssq[tid] = 0.f; }
        __syncthreads();
    }

    float ls[16], ls2[16];
#pragma unroll
    for (int q = 0; q < 16; q++) { ls[q] = 0.f; ls2[q] = 0.f; }

    int r0l = lane >> 2, c0l = (lane & 3) * 2;
#pragma unroll
    for (int im = 0; im < 2; im++) {
#pragma unroll
        for (int jn = 0; jn < 8; jn++) {
            int col = nBase + wn * 64 + jn * 8 + c0l;
            float bv0 = bias[col], bv1 = bias[col + 1];
#pragma unroll
            for (int hf = 0; hf < 2; hf++) {
                int row = rowBase + wm * 32 + im * 16 + r0l + hf * 8;
                if (full || row < M) {
                    float v0 = fmaxf(acc[im][jn][hf * 2 + 0] + bv0, 0.f);
                    float v1 = fmaxf(acc[im][jn][hf * 2 + 1] + bv1, 0.f);
                    if (statsOut) {
                        ls[jn * 2 + 0] += v0; ls2[jn * 2 + 0] += v0 * v0;
                        ls[jn * 2 + 1] += v1; ls2[jn * 2 + 1] += v1 * v1;
                    }
                    __half h0 = __float2half_rn(v0), h1 = __float2half_rn(v1);
                    __half l0 = __float2half_rn(v0 - __half2float(h0));
                    __half l1 = __float2half_rn(v1 - __half2float(h1));
                    size_t o = (size_t)row * Nfull + col;
                    *(__half2*)&Chi[o] = __halves2half2(h0, h1);
                    *(__half2*)&Clo[o] = __halves2half2(l0, l1);
                }
            }
        }
    }

    if (statsOut) {
#pragma unroll
        for (int jn = 0; jn < 8; jn++) {
#pragma unroll
            for (int cc = 0; cc < 2; cc++) {
                int col = wn * 64 + jn * 8 + c0l + cc;
                atomicAdd(&ssum[col], ls[jn * 2 + cc]);
                atomicAdd(&ssq[col],  ls2[jn * 2 + cc]);
            }
        }
        __syncthreads();
        if (tid < 128) {
            atomicAdd(&statsOut[tid],       ssum[tid]);
            atomicAdd(&statsOut[128 + tid], ssq[tid]);
        }
    }
}

// ---------------- fp32 SGEMM (head only) ----------------
__global__ __launch_bounds__(256, 2)
void sgemm_kernel(const float* __restrict__ A, const float* __restrict__ W,
                  const float* __restrict__ bias, float* __restrict__ C,
                  int M, int K, int Nout, int mode) {
    __shared__ float As[8][128];
    __shared__ float Bs[8][128];

    int tid     = threadIdx.x;
    int rowBase = blockIdx.x * 128;
    int colBase = blockIdx.y * 128;

    int aRow = tid >> 1;
    int aCol = (tid & 1) * 4;
    int bRow = tid >> 5;
    int bCol = (tid & 31) * 4;
    int tr = (tid >> 4) * 8;
    int tc = (tid & 15) * 8;

    unsigned long long acc[8][4];
#pragma unroll
    for (int i = 0; i < 8; i++)
#pragma unroll
        for (int j = 0; j < 4; j++) acc[i][j] = 0ull;

    bool aValid = (rowBase + aRow) < M;
    const float* Aptr = A + (size_t)(rowBase + aRow) * K + aCol;
    const float* Wptr = W + (size_t)bRow * Nout + colBase + bCol;

    for (int k0 = 0; k0 < K; k0 += 8) {
        float4 av = make_float4(0.f, 0.f, 0.f, 0.f);
        if (aValid) av = *(const float4*)(Aptr + k0);
        As[aCol + 0][aRow] = av.x;
        As[aCol + 1][aRow] = av.y;
        As[aCol + 2][aRow] = av.z;
        As[aCol + 3][aRow] = av.w;
        float4 bv = *(const float4*)(Wptr + (size_t)k0 * Nout);
        *(float4*)&Bs[bRow][bCol] = bv;
        __syncthreads();

#pragma unroll
        for (int k = 0; k < 8; k++) {
            float4 af0 = *(const float4*)&As[k][tr];
            float4 af1 = *(const float4*)&As[k][tr + 4];
            float ar[8] = {af0.x, af0.y, af0.z, af0.w, af1.x, af1.y, af1.z, af1.w};
            ulonglong2 b01 = *(const ulonglong2*)&Bs[k][tc];
            ulonglong2 b23 = *(const ulonglong2*)&Bs[k][tc + 4];
            unsigned long long bp0 = b01.x, bp1 = b01.y, bp2 = b23.x, bp3 = b23.y;
#pragma unroll
            for (int i = 0; i < 8; i++) {
                unsigned long long a2;
                PACK2(a2, ar[i]);
                FMA2(acc[i][0], a2, bp0, acc[i][0]);
                FMA2(acc[i][1], a2, bp1, acc[i][1]);
                FMA2(acc[i][2], a2, bp2, acc[i][2]);
                FMA2(acc[i][3], a2, bp3, acc[i][3]);
            }
        }
        __syncthreads();
    }

#pragma unroll
    for (int i = 0; i < 8; i++) {
        int r = rowBase + tr + i;
        if (r >= M) break;
#pragma unroll
        for (int j = 0; j < 4; j++) {
            int c  = colBase + tc + 2 * j;
            float v0 = __uint_as_float((unsigned)(acc[i][j]));
            float v1 = __uint_as_float((unsigned)(acc[i][j] >> 32));
            v0 += bias[c];
            v1 += bias[c + 1];
            if (mode == 1) { v0 = fmaxf(v0, 0.f); v1 = fmaxf(v1, 0.f); }
            *(float2*)&C[(size_t)r * Nout + c] = make_float2(v0, v1);
        }
    }
}

// bn apply (2-row unrolled, 128 thr); h += bn(u); colmin; segment-sum into G
__global__ void bn_apply_kernel(const __half* __restrict__ uhi,
                                const __half* __restrict__ ulo,
                                const float* __restrict__ stats,
                                const float* __restrict__ gamma,
                                const float* __restrict__ beta, float invM,
                                const int* __restrict__ mem,
                                float* __restrict__ G, int gOff,
                                float* __restrict__ h,
                                unsigned* __restrict__ cminOut) {
    int r0 = blockIdx.x * RPB;
    if (r0 >= NNODES) return;
    int r1 = min(r0 + RPB, NNODES);
    int c = threadIdx.x;
    float mean = stats[c] * invM;
    float var  = stats[DIM + c] * invM - mean * mean;
    float sc   = gamma[c] * rsqrtf(var + BN_EPS);
    float bb   = beta[c];
    unsigned best = 0xFFFFFFFFu;
    int curg = mem[r0];
    float acc = 0.f;
    int r = r0;
    for (; r + 1 < r1; r += 2) {
        size_t o0 = (size_t)r * DIM + c, o1 = o0 + DIM;
        float uh0 = __half2float(uhi[o0]), ul0 = __half2float(ulo[o0]);
        float uh1 = __half2float(uhi[o1]), ul1 = __half2float(ulo[o1]);
        float h0 = h[o0], h1 = h[o1];
        int g0 = mem[r], g1 = mem[r + 1];
        float v0 = (uh0 + ul0 - mean) * sc + bb;
        float v1 = (uh1 + ul1 - mean) * sc + bb;
        if (g0 != curg) {
            atomicAdd(&G[(size_t)curg * CATW + gOff + c], acc);
            acc = 0.f; curg = g0;
        }
        acc += v0;
        if (g1 != curg) {
            atomicAdd(&G[(size_t)curg * CATW + gOff + c], acc);
            acc = 0.f; curg = g1;
        }
        acc += v1;
        float hn0 = h0 + v0, hn1 = h1 + v1;
        h[o0] = hn0;
        h[o1] = hn1;
        best = min(best, min(f2o(hn0), f2o(hn1)));
    }
    if (r < r1) {
        size_t o = (size_t)r * DIM + c;
        float u = __half2float(uhi[o]) + __half2float(ulo[o]);
        float v = (u - mean) * sc + bb;
        int g = mem[r];
        if (g != curg) {
            atomicAdd(&G[(size_t)curg * CATW + gOff + c], acc);
            acc = 0.f; curg = g;
        }
        acc += v;
        float hn = h[o] + v;
        h[o] = hn;
        best = min(best, f2o(hn));
    }
    atomicAdd(&G[(size_t)curg * CATW + gOff + c], acc);
    atomicMin(&cminOut[c], best);
}

__global__ void final_kernel(const float* __restrict__ X,
                             const float* __restrict__ stats,
                             const float* __restrict__ g0,
                             const float* __restrict__ b0,
                             const float* __restrict__ w,
                             const float* __restrict__ b2,
                             float* __restrict__ out) {
    int warp = threadIdx.x >> 5;
    int lane = threadIdx.x & 31;
    int r = blockIdx.x * 8 + warp;
    if (r >= NGRAPHS) return;
    const float invM = 1.0f / NGRAPHS;
    float acc = 0.f;
#pragma unroll
    for (int j = 0; j < 4; j++) {
        int c = lane + j * 32;
        float mean = stats[c] * invM;
        float var  = stats[DIM + c] * invM - mean * mean;
        float v = (X[(size_t)r * DIM + c] - mean) * g0[c] * rsqrtf(var + BN_EPS) + b0[c];
        acc += v * w[c];
    }
#pragma unroll
    for (int o = 16; o > 0; o >>= 1) acc += __shfl_down_sync(0xFFFFFFFFu, acc, o);
    if (lane == 0) out[r] = acc + b2[0];
}

// ---------------- launch ----------------
extern "C" void kernel_launch(void* const* d_in, const int* in_sizes, int n_in,
                              void* d_out, int out_size) {
    const float* x         = (const float*)d_in[0];
    const int*   nbrs      = (const int*)d_in[1];
    const int*   membership= (const int*)d_in[2];
    const float* merge_W   = (const float*)d_in[3];
    const float* merge_b   = (const float*)d_in[4];
    const float* lin1_W    = (const float*)d_in[5];
    const float* lin1_b    = (const float*)d_in[6];
    const float* lin2_W    = (const float*)d_in[7];
    const float* lin2_b    = (const float*)d_in[8];
    const float* bn_g      = (const float*)d_in[9];
    const float* bn_b      = (const float*)d_in[10];
    const float* epsv      = (const float*)d_in[11];
    const float* dense0_W  = (const float*)d_in[12];
    const float* dense0_b  = (const float*)d_in[13];
    const float* dense1_W  = (const float*)d_in[14];
    const float* dense1_b  = (const float*)d_in[15];
    const float* bn0_g     = (const float*)d_in[16];
    const float* bn0_b     = (const float*)d_in[17];
    const float* dense2_W  = (const float*)d_in[18];
    const float* dense2_b  = (const float*)d_in[19];
    float* out = (float*)d_out;

    float *hP, *aggrP, *zP, *tP, *statsP, *gP, *g1P, *g2P;
    __half *whiP, *wloP;
    unsigned* cminP;
    cudaGetSymbolAddress((void**)&hP, d_h);
    cudaGetSymbolAddress((void**)&aggrP, d_aggr);
    cudaGetSymbolAddress((void**)&zP, d_zA);
    cudaGetSymbolAddress((void**)&tP, d_tB);
    cudaGetSymbolAddress((void**)&statsP, d_stats);
    cudaGetSymbolAddress((void**)&gP, d_g);
    cudaGetSymbolAddress((void**)&g1P, d_g1);
    cudaGetSymbolAddress((void**)&g2P, d_g2);
    cudaGetSymbolAddress((void**)&cminP, d_cminu);
    cudaGetSymbolAddress((void**)&whiP, d_wthi);
    cudaGetSymbolAddress((void**)&wloP, d_wtlo);

    __half* aggrHi = (__half*)aggrP;
    __half* aggrLo = aggrHi + (size_t)NNODES * 256;
    __half* uHi    = (__half*)zP;
    __half* uLo    = uHi + (size_t)NNODES * 128;
    __half* tHi    = (__half*)tP;
    __half* tLo    = tHi + (size_t)NNODES * 256;

    static int smemSet = 0;
    if (!smemSet) {
        cudaFuncSetAttribute(hmma_gemm_kernel,
                             cudaFuncAttributeMaxDynamicSharedMemorySize, 2 * BUFSZ);
        cudaFuncSetAttribute(fused_gemm12_kernel,
                             cudaFuncAttributeMaxDynamicSharedMemorySize, SMEM_FUSED);
        smemSet = 1;
    }

    const int mTiles = (NNODES + 127) / 128;  // 782
    const int SM = 2 * BUFSZ;                 // 75776

    wsplit_kernel<<<1920, 256>>>(merge_W, lin1_W, lin2_W, whiP, wloP);

    fill_u32_kernel<<<(NGRAPHS * CATW + 255) / 256, 256>>>((unsigned*)gP, 0u,
                                                           NGRAPHS * CATW);
    reset_kernel<<<1, 384>>>(statsP, cminP);
    init_kernel<<<SEGBLK, 128>>>(x, hP, membership, gP, cminP);

    for (int i = 0; i < NBLOCKS; i++) {
        aggregate_kernel<<<(NNODES + 15) / 16, 256>>>(hP, nbrs, cminP, aggrHi,
                                                      aggrLo);

        fused_gemm12_kernel<<<mTiles, 256, SMEM_FUSED>>>(
            aggrHi, aggrLo,
            whiP + (size_t)(3 * i + 0) * 32768, wloP + (size_t)(3 * i + 0) * 32768,
            merge_b + i * DIM,
            whiP + (size_t)(3 * i + 1) * 32768, wloP + (size_t)(3 * i + 1) * 32768,
            lin1_b + i * HIDDEN,
            tHi, tLo, NNODES, hP, epsv, i, statsP);

        hmma_gemm_kernel<<<dim3(mTiles, 1), 256, SM>>>(
            tHi, tLo,
            whiP + (size_t)(3 * i + 2) * 32768, wloP + (size_t)(3 * i + 2) * 32768,
            lin2_b + i * DIM, uHi, uLo, NNODES, 256, 128, statsP, cminP);

        bn_apply_kernel<<<SEGBLK, 128>>>(uHi, uLo, statsP, bn_g + i * DIM,
                                         bn_b + i * DIM, 1.0f / NNODES,
                                         membership, gP, (i + 1) * DIM, hP, cminP);
    }

    sgemm_kernel<<<dim3(NGRAPHS / 128, 2), 256>>>(
        gP, dense0_W, dense0_b, g1P, NGRAPHS, CATW, HIDDEN, 1);
    sgemm_kernel<<<dim3(NGRAPHS / 128, 1), 256>>>(
        g1P, dense1_W, dense1_b, g2P, NGRAPHS, HIDDEN, DIM, 1);

    reset_kernel<<<1, 384>>>(statsP, cminP);
    colstats_kernel<<<64, 128>>>(g2P, NGRAPHS, statsP);
    final_kernel<<<NGRAPHS / 8, 256>>>(g2P, statsP, bn0_g, bn0_b, dense2_W,
                                       dense2_b, out);
}

// round 17
// speedup vs baseline: 1.4910x; 1.4910x over previous
// R17: re-bench of the R13-optimum configuration (no functional change).
#include <cuda_runtime.h>
#include <cuda_fp16.h>
#include <cstdint>

#define NNODES   100000
#define MAXDEG   16
#define DIM      128
#define HIDDEN   256
#define NBLOCKS  5
#define NGRAPHS  2048
#define CATW     (DIM * (NBLOCKS + 1))   // 768
#define BN_EPS   1e-5f
#define RPB      49
#define SEGBLK   ((NNODES + RPB - 1) / RPB)   // 2041

// ---------------- scratch ----------------
__device__ float    d_h[(size_t)NNODES * DIM];
__device__ float    d_aggr[(size_t)NNODES * 2 * DIM];
__device__ float    d_zA[(size_t)NNODES * DIM];
__device__ float    d_tB[(size_t)NNODES * HIDDEN];
__device__ unsigned d_cminu[DIM];
__device__ float    d_stats[2 * DIM];
__device__ float    d_g[(size_t)NGRAPHS * CATW];
__device__ float    d_g1[(size_t)NGRAPHS * HIDDEN];
__device__ float    d_g2[(size_t)NGRAPHS * DIM];
__device__ __half   d_wthi[15 * 32768];
__device__ __half   d_wtlo[15 * 32768];

// ---------------- helpers ----------------
#define FMA2(d, a, b, c) \
    asm("fma.rn.f32x2 %0, %1, %2, %3;" : "=l"(d) : "l"(a), "l"(b), "l"(c))
#define PACK2(d, x) \
    asm("mov.b64 %0, {%1, %1};" : "=l"(d) : "f"(x))

__device__ __forceinline__ unsigned f2o(float f) {
    unsigned u = __float_as_uint(f);
    return (u & 0x80000000u) ? ~u : (u | 0x80000000u);
}
__device__ __forceinline__ float o2f(unsigned o) {
    unsigned u = (o & 0x80000000u) ? (o & 0x7FFFFFFFu) : ~o;
    return __uint_as_float(u);
}
__device__ __forceinline__ uint32_t s2u(const void* p) {
    uint32_t a;
    asm("{ .reg .u64 t; cvta.to.shared.u64 t, %1; cvt.u32.u64 %0, t; }"
        : "=r"(a) : "l"(p));
    return a;
}

#define LDSM_X4(r0, r1, r2, r3, addr) \
    asm volatile("ldmatrix.sync.aligned.m8n8.x4.shared.b16 {%0,%1,%2,%3}, [%4];" \
        : "=r"(r0), "=r"(r1), "=r"(r2), "=r"(r3) : "r"(addr))
#define LDSM_X4T(r0, r1, r2, r3, addr) \
    asm volatile("ldmatrix.sync.aligned.m8n8.x4.trans.shared.b16 {%0,%1,%2,%3}, [%4];" \
        : "=r"(r0), "=r"(r1), "=r"(r2), "=r"(r3) : "r"(addr))
#define MMA16816(c, a, b0, b1) \
    asm volatile("mma.sync.aligned.m16n8k16.row.col.f32.f16.f16.f32 " \
        "{%0,%1,%2,%3}, {%4,%5,%6,%7}, {%8,%9}, {%0,%1,%2,%3};" \
        : "+f"((c)[0]), "+f"((c)[1]), "+f"((c)[2]), "+f"((c)[3]) \
        : "r"((a)[0]), "r"((a)[1]), "r"((a)[2]), "r"((a)[3]), "r"(b0), "r"(b1))
#define CP16(dst, src) \
    asm volatile("cp.async.cg.shared.global [%0], [%1], 16;" :: "r"(dst), "l"(src))
#define CP_COMMIT() asm volatile("cp.async.commit_group;")
#define CP_WAIT(n)  asm volatile("cp.async.wait_group %0;" :: "n"(n))

#define OFF_AL 10240
#define OFF_BH 20480
#define BUFSZ  37888
#define ZCH    20480
#define P2B    81920
#define SMEM_FUSED (P2B + 17408)   // 99328

// ---------------- small utility kernels ----------------
__global__ void fill_u32_kernel(unsigned* p, unsigned v, int n) {
    int i = blockIdx.x * blockDim.x + threadIdx.x;
    if (i < n) p[i] = v;
}

__global__ void reset_kernel(float* stats, unsigned* cmin) {
    int t = threadIdx.x;
    if (t < 256) stats[t] = 0.f;
    else cmin[t - 256] = 0xFFFFFFFFu;
}

// h = x; colmin(x); segment-sum x into G[:,0:128]   (2-row unrolled, 128 thr)
__global__ void init_kernel(const float* __restrict__ x,
                            float* __restrict__ h,
                            const int* __restrict__ mem,
                            float* __restrict__ G,
                            unsigned* __restrict__ cmin) {
    int r0 = blockIdx.x * RPB;
    if (r0 >= NNODES) return;
    int r1 = min(r0 + RPB, NNODES);
    int c = threadIdx.x;
    unsigned best = 0xFFFFFFFFu;
    int curg = mem[r0];
    float acc = 0.f;
    int r = r0;
    for (; r + 1 < r1; r += 2) {
        size_t o0 = (size_t)r * DIM + c, o1 = o0 + DIM;
        float v0 = x[o0];
        float v1 = x[o1];
        int g0 = mem[r], g1 = mem[r + 1];
        h[o0] = v0;
        h[o1] = v1;
        best = min(best, min(f2o(v0), f2o(v1)));
        if (g0 != curg) {
            atomicAdd(&G[(size_t)curg * CATW + c], acc);
            acc = 0.f; curg = g0;
        }
        acc += v0;
        if (g1 != curg) {
            atomicAdd(&G[(size_t)curg * CATW + c], acc);
            acc = 0.f; curg = g1;
        }
        acc += v1;
    }
    if (r < r1) {
        size_t o = (size_t)r * DIM + c;
        float v = x[o];
        h[o] = v;
        best = min(best, f2o(v));
        int g = mem[r];
        if (g != curg) {
            atomicAdd(&G[(size_t)curg * CATW + c], acc);
            acc = 0.f; curg = g;
        }
        acc += v;
    }
    atomicAdd(&G[(size_t)curg * CATW + c], acc);
    atomicMin(&cmin[c], best);
}

__global__ void wsplit_kernel(const float* __restrict__ mW,
                              const float* __restrict__ l1W,
                              const float* __restrict__ l2W,
                              __half* __restrict__ whi, __half* __restrict__ wlo) {
    int i = blockIdx.x * 256 + threadIdx.x;
    if (i >= 15 * 32768) return;
    int slot = i >> 15;
    int e = i & 32767;
    int b = slot / 3, m = slot - 3 * b;
    const float* W = (m == 0) ? mW + (size_t)b * 32768
                   : (m == 1) ? l1W + (size_t)b * 32768
                              : l2W + (size_t)b * 32768;
    float w = W[e];
    __half hi = __float2half_rn(w);
    __half lo = __float2half_rn(w - __half2float(hi));
    whi[i] = hi;
    wlo[i] = lo;
}

__global__ void colstats_kernel(const float* __restrict__ X, int M,
                                float* __restrict__ stats) {
    int c = threadIdx.x;
    float s = 0.f, s2 = 0.f;
    for (int r = blockIdx.x; r < M; r += gridDim.x) {
        float v = X[(size_t)r * DIM + c];
        s += v; s2 += v * v;
    }
    atomicAdd(&stats[c], s);
    atomicAdd(&stats[DIM + c], s2);
}

// fused sum+max aggregation; 2 nodes per warp; packed 16B split stores.
__global__ void aggregate_kernel(const float* __restrict__ H,
                                 const int* __restrict__ nbrs,
                                 const unsigned* __restrict__ cminu,
                                 __half* __restrict__ aHi,
                                 __half* __restrict__ aLo) {
    int warp = threadIdx.x >> 5;
    int lane = threadIdx.x & 31;
    int node0 = blockIdx.x * 16 + warp * 2;
    int node1 = node0 + 1;
    if (node0 >= NNODES) return;
    bool has1 = (node1 < NNODES);

    float4 mm[2], ss[2];
    mm[0].x = o2f(cminu[lane * 4 + 0]);
    mm[0].y = o2f(cminu[lane * 4 + 1]);
    mm[0].z = o2f(cminu[lane * 4 + 2]);
    mm[0].w = o2f(cminu[lane * 4 + 3]);
    mm[1] = mm[0];
    ss[0] = make_float4(0.f, 0.f, 0.f, 0.f);
    ss[1] = ss[0];

    int idx0[MAXDEG], idx1[MAXDEG];
    const int* nb0 = nbrs + (size_t)node0 * MAXDEG;
    const int* nb1 = nbrs + (size_t)(has1 ? node1 : node0) * MAXDEG;
#pragma unroll
    for (int j = 0; j < MAXDEG; j++) idx0[j] = __ldg(&nb0[j]);
#pragma unroll
    for (int j = 0; j < MAXDEG; j++) idx1[j] = __ldg(&nb1[j]);

    const float4* H4 = (const float4*)H;
#pragma unroll
    for (int g = 0; g < 2; g++) {
        float4 v0[8], v1[8];
#pragma unroll
        for (int j = 0; j < 8; j++) {
            int n = idx0[g * 8 + j];
            v0[j] = H4[(size_t)(n >= 0 ? n : node0) * 32 + lane];
        }
#pragma unroll
        for (int j = 0; j < 8; j++) {
            int n = idx1[g * 8 + j];
            v1[j] = H4[(size_t)(n >= 0 ? n : node0) * 32 + lane];
        }
#pragma unroll
        for (int j = 0; j < 8; j++) {
            if (idx0[g * 8 + j] >= 0) {
                float4 v = v0[j];
                ss[0].x += v.x; ss[0].y += v.y; ss[0].z += v.z; ss[0].w += v.w;
                mm[0].x = fmaxf(mm[0].x, v.x); mm[0].y = fmaxf(mm[0].y, v.y);
                mm[0].z = fmaxf(mm[0].z, v.z); mm[0].w = fmaxf(mm[0].w, v.w);
            }
        }
#pragma unroll
        for (int j = 0; j < 8; j++) {
            if (idx1[g * 8 + j] >= 0) {
                float4 v = v1[j];
                ss[1].x += v.x; ss[1].y += v.y; ss[1].z += v.z; ss[1].w += v.w;
                mm[1].x = fmaxf(mm[1].x, v.x); mm[1].y = fmaxf(mm[1].y, v.y);
                mm[1].z = fmaxf(mm[1].z, v.z); mm[1].w = fmaxf(mm[1].w, v.w);
            }
        }
    }

#pragma unroll
    for (int nn = 0; nn < 2; nn++) {
        if (nn == 1 && !has1) break;
        int node = node0 + nn;
        float sv[8] = {ss[nn].x, ss[nn].y, ss[nn].z, ss[nn].w,
                       mm[nn].x, mm[nn].y, mm[nn].z, mm[nn].w};
#pragma unroll
        for (int q = 0; q < 2; q++) {
            __half h0 = __float2half_rn(sv[q * 4 + 0]);
            __half h1 = __float2half_rn(sv[q * 4 + 1]);
            __half h2 = __float2half_rn(sv[q * 4 + 2]);
            __half h3 = __float2half_rn(sv[q * 4 + 3]);
            __half l0 = __float2half_rn(sv[q * 4 + 0] - __half2float(h0));
            __half l1 = __float2half_rn(sv[q * 4 + 1] - __half2float(h1));
            __half l2 = __float2half_rn(sv[q * 4 + 2] - __half2float(h2));
            __half l3 = __float2half_rn(sv[q * 4 + 3] - __half2float(h3));
            size_t off = (size_t)node * 256 + q * 128 + lane * 4;
            uint2 ph, pl;
            __half2 t0 = __halves2half2(h0, h1), t1 = __halves2half2(h2, h3);
            ph.x = *(uint32_t*)&t0; ph.y = *(uint32_t*)&t1;
            __half2 t2 = __halves2half2(l0, l1), t3 = __halves2half2(l2, l3);
            pl.x = *(uint32_t*)&t2; pl.y = *(uint32_t*)&t3;
            *(uint2*)&aHi[off] = ph;
            *(uint2*)&aLo[off] = pl;
        }
    }
}

// ============ shared GEMM building blocks ====================================
__device__ __forceinline__ void fillB(uint32_t bufBH, const __half* Bh,
                                      const __half* Bl, int k0, int Nfull,
                                      int nBase, int tid) {
#pragma unroll
    for (int i = 0; i < 2; i++) {
        int idx = tid + 256 * i;
        int k = idx >> 4, c = idx & 15;
        uint32_t d = k * 272 + c * 16;
        size_t srcOff = (size_t)(k0 + k) * Nfull + nBase + c * 8;
        CP16(bufBH + d, Bh + srcOff);
        CP16(bufBH + 8704 + d, Bl + srcOff);
    }
}

template <bool FULL>
__device__ __forceinline__ void fillA(uint32_t buf, const __half* Ahi,
                                      const __half* Alo, int M, int K,
                                      int rowBase, int k0, int tid) {
#pragma unroll
    for (int i = 0; i < 2; i++) {
        int idx = tid + 256 * i;
        int r = idx >> 2, c16 = idx & 3;
        if (FULL || rowBase + r < M) {
            size_t srcOff = (size_t)(rowBase + r) * K + k0 + c16 * 8;
            uint32_t d = r * 80 + c16 * 16;
            CP16(buf + d, Ahi + srcOff);
            CP16(buf + OFF_AL + d, Alo + srcOff);
        }
    }
}

// 32 K-cols of 3-product MMA, fp32 accumulate
__device__ __forceinline__ void mma_chunk(uint32_t abuf, uint32_t bbuf,
                                          int lane, int wm, int wn,
                                          float (&acc)[2][8][4]) {
    const int lr = lane & 15, lc = lane >> 4;
#pragma unroll
    for (int ks = 0; ks < 2; ks++) {
        uint32_t ah[2][4], al[2][4];
#pragma unroll
        for (int im = 0; im < 2; im++) {
            uint32_t aoff = (uint32_t)(wm * 32 + im * 16 + lr) * 80 + ks * 32 + lc * 16;
            LDSM_X4(ah[im][0], ah[im][1], ah[im][2], ah[im][3], abuf + aoff);
            LDSM_X4(al[im][0], al[im][1], al[im][2], al[im][3], abuf + OFF_AL + aoff);
        }
        uint32_t boff = (uint32_t)(ks * 16 + lr) * 272 + lc * 16 + wn * 128;
#pragma unroll
        for (int ng = 0; ng < 4; ng++) {
            uint32_t bh0, bh1, bh2, bh3;
            LDSM_X4T(bh0, bh1, bh2, bh3, bbuf + boff + ng * 32);
#pragma unroll
            for (int im = 0; im < 2; im++) {
                MMA16816(acc[im][ng * 2 + 0], ah[im], bh0, bh1);
                MMA16816(acc[im][ng * 2 + 1], ah[im], bh2, bh3);
            }
#pragma unroll
            for (int im = 0; im < 2; im++) {
                MMA16816(acc[im][ng * 2 + 0], al[im], bh0, bh1);
                MMA16816(acc[im][ng * 2 + 1], al[im], bh2, bh3);
            }
            uint32_t bl0, bl1, bl2, bl3;
            LDSM_X4T(bl0, bl1, bl2, bl3, bbuf + 8704 + boff + ng * 32);
#pragma unroll
            for (int im = 0; im < 2; im++) {
                MMA16816(acc[im][ng * 2 + 0], ah[im], bl0, bl1);
                MMA16816(acc[im][ng * 2 + 1], ah[im], bl2, bl3);
            }
        }
    }
}

// ============ fused GEMM1+GEMM2 ==============================================
__global__ __launch_bounds__(256, 2)
void fused_gemm12_kernel(const __half* __restrict__ Ahi, const __half* __restrict__ Alo,
                         const __half* __restrict__ W0h, const __half* __restrict__ W0l,
                         const float* __restrict__ b0v,
                         const __half* __restrict__ W1h, const __half* __restrict__ W1l,
                         const float* __restrict__ b1v,
                         __half* __restrict__ tHi, __half* __restrict__ tLo,
                         int M, const float* __restrict__ hsrc,
                         const float* __restrict__ epsv, int blk,
                         float* __restrict__ statsReset) {
    extern __shared__ char smem[];
    const uint32_t sb = s2u(smem);
    const int tid = threadIdx.x;
    const int lane = tid & 31, wid = tid >> 5;
    const int wm = wid >> 1, wn = wid & 1;
    const int rowBase = blockIdx.x * 128;
    const bool full = (rowBase + 128 <= M);
    const int r0l = lane >> 2, c0l = (lane & 3) * 2;

    if (blockIdx.x == 0 && statsReset) statsReset[tid] = 0.f;

    float acc[2][8][4];
#pragma unroll
    for (int i = 0; i < 2; i++)
#pragma unroll
        for (int j = 0; j < 8; j++)
#pragma unroll
            for (int k = 0; k < 4; k++) acc[i][j][k] = 0.f;

    if (full) fillA<true>(sb, Ahi, Alo, M, 256, rowBase, 0, tid);
    else      fillA<false>(sb, Ahi, Alo, M, 256, rowBase, 0, tid);
    fillB(sb + OFF_BH, W0h, W0l, 0, 128, 0, tid);
    CP_COMMIT();

    for (int c = 0; c < 8; c++) {
        int b = c & 1;
        if (c + 1 < 8) {
            uint32_t nb = sb + (b ^ 1) * BUFSZ;
            if (full) fillA<true>(nb, Ahi, Alo, M, 256, rowBase, (c + 1) * 32, tid);
            else      fillA<false>(nb, Ahi, Alo, M, 256, rowBase, (c + 1) * 32, tid);
            fillB(nb + OFF_BH, W0h, W0l, (c + 1) * 32, 128, 0, tid);
            CP_COMMIT();
            CP_WAIT(1);
        } else {
            CP_WAIT(0);
        }
        __syncthreads();
        mma_chunk(sb + b * BUFSZ, sb + b * BUFSZ + OFF_BH, lane, wm, wn, acc);
        __syncthreads();
    }

    // prefetch first phase-2 W1 chunk
    fillB(sb + P2B, W1h, W1l, 0, 256, 0, tid);
    CP_COMMIT();

    {
        float scale = 1.0f + epsv[blk];
#pragma unroll
        for (int im = 0; im < 2; im++) {
#pragma unroll
            for (int jn = 0; jn < 8; jn++) {
                int cloc = wn * 64 + jn * 8 + c0l;
                float bv0 = b0v[cloc], bv1 = b0v[cloc + 1];
                int kc = cloc >> 5, cc = cloc & 31;
#pragma unroll
                for (int hf = 0; hf < 2; hf++) {
                    int rloc = wm * 32 + im * 16 + r0l + hf * 8;
                    int row = rowBase + rloc;
                    if (full || row < M) {
                        float v0 = acc[im][jn][hf * 2 + 0] + bv0 +
                                   scale * hsrc[(size_t)row * DIM + cloc];
                        float v1 = acc[im][jn][hf * 2 + 1] + bv1 +
                                   scale * hsrc[(size_t)row * DIM + cloc + 1];
                        __half h0 = __float2half_rn(v0), h1 = __float2half_rn(v1);
                        __half l0 = __float2half_rn(v0 - __half2float(h0));
                        __half l1 = __float2half_rn(v1 - __half2float(h1));
                        char* zp = smem + kc * ZCH + rloc * 80 + cc * 2;
                        *(__half2*)(zp)         = __halves2half2(h0, h1);
                        *(__half2*)(zp + 10240) = __halves2half2(l0, l1);
                    }
                }
            }
        }
    }
    __syncthreads();

#pragma unroll
    for (int nh = 0; nh < 2; nh++) {
        float a2[2][8][4];
#pragma unroll
        for (int i = 0; i < 2; i++)
#pragma unroll
            for (int j = 0; j < 8; j++)
#pragma unroll
                for (int k = 0; k < 4; k++) a2[i][j][k] = 0.f;

        for (int kc = 0; kc < 4; kc++) {
            CP_WAIT(0);
            __syncthreads();
            mma_chunk(sb + kc * ZCH, sb + P2B, lane, wm, wn, a2);
            __syncthreads();
            int it = nh * 4 + kc;
            if (it < 7) {
                int nit = it + 1, nnh = nit >> 2, nkc = nit & 3;
                fillB(sb + P2B, W1h, W1l, nkc * 32, 256, nnh * 128, tid);
                CP_COMMIT();
            }
        }

#pragma unroll
        for (int im = 0; im < 2; im++) {
#pragma unroll
            for (int jn = 0; jn < 8; jn++) {
                int col = nh * 128 + wn * 64 + jn * 8 + c0l;
                float bv0 = b1v[col], bv1 = b1v[col + 1];
#pragma unroll
                for (int hf = 0; hf < 2; hf++) {
                    int row = rowBase + wm * 32 + im * 16 + r0l + hf * 8;
                    if (full || row < M) {
                        float v0 = fmaxf(a2[im][jn][hf * 2 + 0] + bv0, 0.f);
                        float v1 = fmaxf(a2[im][jn][hf * 2 + 1] + bv1, 0.f);
                        __half h0 = __float2half_rn(v0), h1 = __float2half_rn(v1);
                        __half l0 = __float2half_rn(v0 - __half2float(h0));
                        __half l1 = __float2half_rn(v1 - __half2float(h1));
                        size_t o = (size_t)row * HIDDEN + col;
                        *(__half2*)&tHi[o] = __halves2half2(h0, h1);
                        *(__half2*)&tLo[o] = __halves2half2(l0, l1);
                    }
                }
            }
        }
    }
}

// ============ standalone HMMA GEMM (GEMM3) ==================================
__global__ __launch_bounds__(256, 2)
void hmma_gemm_kernel(const __half* __restrict__ Ahi, const __half* __restrict__ Alo,
                      const __half* __restrict__ Bh, const __half* __restrict__ Bl,
                      const float* __restrict__ bias,
                      __half* __restrict__ Chi, __half* __restrict__ Clo,
                      int M, int K, int Nfull,
                      float* __restrict__ statsOut,
                      unsigned* __restrict__ cminReset) {
    extern __shared__ char smem[];
    const uint32_t sb = s2u(smem);
    const int tid = threadIdx.x;
    const int lane = tid & 31, wid = tid >> 5;
    const int wm = wid >> 1, wn = wid & 1;
    const int rowBase = blockIdx.x * 128;
    const int nBase   = blockIdx.y * 128;
    const int NC = K >> 5;
    const bool full = (rowBase + 128 <= M);

    if (blockIdx.x == 0 && blockIdx.y == 0) {
        if (cminReset && tid < 128) cminReset[tid] = 0xFFFFFFFFu;
    }

    float acc[2][8][4];
#pragma unroll
    for (int i = 0; i < 2; i++)
#pragma unroll
        for (int j = 0; j < 8; j++)
#pragma unroll
            for (int k = 0; k < 4; k++) acc[i][j][k] = 0.f;

    if (full) fillA<true>(sb, Ahi, Alo, M, K, rowBase, 0, tid);
    else      fillA<false>(sb, Ahi, Alo, M, K, rowBase, 0, tid);
    fillB(sb + OFF_BH, Bh, Bl, 0, Nfull, nBase, tid);
    CP_COMMIT();

    for (int c = 0; c < NC; c++) {
        int b = c & 1;
        if (c + 1 < NC) {
            uint32_t nb = sb + (b ^ 1) * BUFSZ;
            if (full) fillA<true>(nb, Ahi, Alo, M, K, rowBase, (c + 1) * 32, tid);
            else      fillA<false>(nb, Ahi, Alo, M, K, rowBase, (c + 1) * 32, tid);
            fillB(nb + OFF_BH, Bh, Bl, (c + 1) * 32, Nfull, nBase, tid);
            CP_COMMIT();
            CP_WAIT(1);
        } else {
            CP_WAIT(0);
        }
        __syncthreads();
        mma_chunk(sb + b * BUFSZ, sb + b * BUFSZ + OFF_BH, lane, wm, wn, acc);
        __syncthreads();
    }

    float* ssum = (float*)smem;
    float* ssq  = ssum + 128;
    if (statsOut) {
        if (tid < 128) { ssum[tid] = 0.f; ssq[tid] = 0.f; }
        __syncthreads();
    }

    float ls[16], ls2[16];
#pragma unroll
    for (int q = 0; q < 16; q++) { ls[q] = 0.f; ls2[q] = 0.f; }

    int r0l = lane >> 2, c0l = (lane & 3) * 2;
#pragma unroll
    for (int im = 0; im < 2; im++) {
#pragma unroll
        for (int jn = 0; jn < 8; jn++) {
            int col = nBase + wn * 64 + jn * 8 + c0l;
            float bv0 = bias[col], bv1 = bias[col + 1];
#pragma unroll
            for (int hf = 0; hf < 2; hf++) {
                int row = rowBase + wm * 32 + im * 16 + r0l + hf * 8;
                if (full || row < M) {
                    float v0 = fmaxf(acc[im][jn][hf * 2 + 0] + bv0, 0.f);
                    float v1 = fmaxf(acc[im][jn][hf * 2 + 1] + bv1, 0.f);
                    if (statsOut) {
                        ls[jn * 2 + 0] += v0; ls2[jn * 2 + 0] += v0 * v0;
                        ls[jn * 2 + 1] += v1; ls2[jn * 2 + 1] += v1 * v1;
                    }
                    __half h0 = __float2half_rn(v0), h1 = __float2half_rn(v1);
                    __half l0 = __float2half_rn(v0 - __half2float(h0));
                    __half l1 = __float2half_rn(v1 - __half2float(h1));
                    size_t o = (size_t)row * Nfull + col;
                    *(__half2*)&Chi[o] = __halves2half2(h0, h1);
                    *(__half2*)&Clo[o] = __halves2half2(l0, l1);
                }
            }
        }
    }

    if (statsOut) {
#pragma unroll
        for (int jn = 0; jn < 8; jn++) {
#pragma unroll
            for (int cc = 0; cc < 2; cc++) {
                int col = wn * 64 + jn * 8 + c0l + cc;
                atomicAdd(&ssum[col], ls[jn * 2 + cc]);
                atomicAdd(&ssq[col],  ls2[jn * 2 + cc]);
            }
        }
        __syncthreads();
        if (tid < 128) {
            atomicAdd(&statsOut[tid],       ssum[tid]);
            atomicAdd(&statsOut[128 + tid], ssq[tid]);
        }
    }
}

// ---------------- fp32 SGEMM (head only) ----------------
__global__ __launch_bounds__(256, 2)
void sgemm_kernel(const float* __restrict__ A, const float* __restrict__ W,
                  const float* __restrict__ bias, float* __restrict__ C,
                  int M, int K, int Nout, int mode) {
    __shared__ float As[8][128];
    __shared__ float Bs[8][128];

    int tid     = threadIdx.x;
    int rowBase = blockIdx.x * 128;
    int colBase = blockIdx.y * 128;

    int aRow = tid >> 1;
    int aCol = (tid & 1) * 4;
    int bRow = tid >> 5;
    int bCol = (tid & 31) * 4;
    int tr = (tid >> 4) * 8;
    int tc = (tid & 15) * 8;

    unsigned long long acc[8][4];
#pragma unroll
    for (int i = 0; i < 8; i++)
#pragma unroll
        for (int j = 0; j < 4; j++) acc[i][j] = 0ull;

    bool aValid = (rowBase + aRow) < M;
    const float* Aptr = A + (size_t)(rowBase + aRow) * K + aCol;
    const float* Wptr = W + (size_t)bRow * Nout + colBase + bCol;

    for (int k0 = 0; k0 < K; k0 += 8) {
        float4 av = make_float4(0.f, 0.f, 0.f, 0.f);
        if (aValid) av = *(const float4*)(Aptr + k0);
        As[aCol + 0][aRow] = av.x;
        As[aCol + 1][aRow] = av.y;
        As[aCol + 2][aRow] = av.z;
        As[aCol + 3][aRow] = av.w;
        float4 bv = *(const float4*)(Wptr + (size_t)k0 * Nout);
        *(float4*)&Bs[bRow][bCol] = bv;
        __syncthreads();

#pragma unroll
        for (int k = 0; k < 8; k++) {
            float4 af0 = *(const float4*)&As[k][tr];
            float4 af1 = *(const float4*)&As[k][tr + 4];
            float ar[8] = {af0.x, af0.y, af0.z, af0.w, af1.x, af1.y, af1.z, af1.w};
            ulonglong2 b01 = *(const ulonglong2*)&Bs[k][tc];
            ulonglong2 b23 = *(const ulonglong2*)&Bs[k][tc + 4];
            unsigned long long bp0 = b01.x, bp1 = b01.y, bp2 = b23.x, bp3 = b23.y;
#pragma unroll
            for (int i = 0; i < 8; i++) {
                unsigned long long a2;
                PACK2(a2, ar[i]);
                FMA2(acc[i][0], a2, bp0, acc[i][0]);
                FMA2(acc[i][1], a2, bp1, acc[i][1]);
                FMA2(acc[i][2], a2, bp2, acc[i][2]);
                FMA2(acc[i][3], a2, bp3, acc[i][3]);
            }
        }
        __syncthreads();
    }

#pragma unroll
    for (int i = 0; i < 8; i++) {
        int r = rowBase + tr + i;
        if (r >= M) break;
#pragma unroll
        for (int j = 0; j < 4; j++) {
            int c  = colBase + tc + 2 * j;
            float v0 = __uint_as_float((unsigned)(acc[i][j]));
            float v1 = __uint_as_float((unsigned)(acc[i][j] >> 32));
            v0 += bias[c];
            v1 += bias[c + 1];
            if (mode == 1) { v0 = fmaxf(v0, 0.f); v1 = fmaxf(v1, 0.f); }
            *(float2*)&C[(size_t)r * Nout + c] = make_float2(v0, v1);
        }
    }
}

// bn apply (2-row unrolled, 128 thr); h += bn(u); colmin; segment-sum into G
__global__ void bn_apply_kernel(const __half* __restrict__ uhi,
                                const __half* __restrict__ ulo,
                                const float* __restrict__ stats,
                                const float* __restrict__ gamma,
                                const float* __restrict__ beta, float invM,
                                const int* __restrict__ mem,
                                float* __restrict__ G, int gOff,
                                float* __restrict__ h,
                                unsigned* __restrict__ cminOut) {
    int r0 = blockIdx.x * RPB;
    if (r0 >= NNODES) return;
    int r1 = min(r0 + RPB, NNODES);
    int c = threadIdx.x;
    float mean = stats[c] * invM;
    float var  = stats[DIM + c] * invM - mean * mean;
    float sc   = gamma[c] * rsqrtf(var + BN_EPS);
    float bb   = beta[c];
    unsigned best = 0xFFFFFFFFu;
    int curg = mem[r0];
    float acc = 0.f;
    int r = r0;
    for (; r + 1 < r1; r += 2) {
        size_t o0 = (size_t)r * DIM + c, o1 = o0 + DIM;
        float uh0 = __half2float(uhi[o0]), ul0 = __half2float(ulo[o0]);
        float uh1 = __half2float(uhi[o1]), ul1 = __half2float(ulo[o1]);
        float h0 = h[o0], h1 = h[o1];
        int g0 = mem[r], g1 = mem[r + 1];
        float v0 = (uh0 + ul0 - mean) * sc + bb;
        float v1 = (uh1 + ul1 - mean) * sc + bb;
        if (g0 != curg) {
            atomicAdd(&G[(size_t)curg * CATW + gOff + c], acc);
            acc = 0.f; curg = g0;
        }
        acc += v0;
        if (g1 != curg) {
            atomicAdd(&G[(size_t)curg * CATW + gOff + c], acc);
            acc = 0.f; curg = g1;
        }
        acc += v1;
        float hn0 = h0 + v0, hn1 = h1 + v1;
        h[o0] = hn0;
        h[o1] = hn1;
        best = min(best, min(f2o(hn0), f2o(hn1)));
    }
    if (r < r1) {
        size_t o = (size_t)r * DIM + c;
        float u = __half2float(uhi[o]) + __half2float(ulo[o]);
        float v = (u - mean) * sc + bb;
        int g = mem[r];
        if (g != curg) {
            atomicAdd(&G[(size_t)curg * CATW + gOff + c], acc);
            acc = 0.f; curg = g;
        }
        acc += v;
        float hn = h[o] + v;
        h[o] = hn;
        best = min(best, f2o(hn));
    }
    atomicAdd(&G[(size_t)curg * CATW + gOff + c], acc);
    atomicMin(&cminOut[c], best);
}

__global__ void final_kernel(const float* __restrict__ X,
                             const float* __restrict__ stats,
                             const float* __restrict__ g0,
                             const float* __restrict__ b0,
                             const float* __restrict__ w,
                             const float* __restrict__ b2,
                             float* __restrict__ out) {
    int warp = threadIdx.x >> 5;
    int lane = threadIdx.x & 31;
    int r = blockIdx.x * 8 + warp;
    if (r >= NGRAPHS) return;
    const float invM = 1.0f / NGRAPHS;
    float acc = 0.f;
#pragma unroll
    for (int j = 0; j < 4; j++) {
        int c = lane + j * 32;
        float mean = stats[c] * invM;
        float var  = stats[DIM + c] * invM - mean * mean;
        float v = (X[(size_t)r * DIM + c] - mean) * g0[c] * rsqrtf(var + BN_EPS) + b0[c];
        acc += v * w[c];
    }
#pragma unroll
    for (int o = 16; o > 0; o >>= 1) acc += __shfl_down_sync(0xFFFFFFFFu, acc, o);
    if (lane == 0) out[r] = acc + b2[0];
}

// ---------------- launch ----------------
extern "C" void kernel_launch(void* const* d_in, const int* in_sizes, int n_in,
                              void* d_out, int out_size) {
    const float* x         = (const float*)d_in[0];
    const int*   nbrs      = (const int*)d_in[1];
    const int*   membership= (const int*)d_in[2];
    const float* merge_W   = (const float*)d_in[3];
    const float* merge_b   = (const float*)d_in[4];
    const float* lin1_W    = (const float*)d_in[5];
    const float* lin1_b    = (const float*)d_in[6];
    const float* lin2_W    = (const float*)d_in[7];
    const float* lin2_b    = (const float*)d_in[8];
    const float* bn_g      = (const float*)d_in[9];
    const float* bn_b      = (const float*)d_in[10];
    const float* epsv      = (const float*)d_in[11];
    const float* dense0_W  = (const float*)d_in[12];
    const float* dense0_b  = (const float*)d_in[13];
    const float* dense1_W  = (const float*)d_in[14];
    const float* dense1_b  = (const float*)d_in[15];
    const float* bn0_g     = (const float*)d_in[16];
    const float* bn0_b     = (const float*)d_in[17];
    const float* dense2_W  = (const float*)d_in[18];
    const float* dense2_b  = (const float*)d_in[19];
    float* out = (float*)d_out;

    float *hP, *aggrP, *zP, *tP, *statsP, *gP, *g1P, *g2P;
    __half *whiP, *wloP;
    unsigned* cminP;
    cudaGetSymbolAddress((void**)&hP, d_h);
    cudaGetSymbolAddress((void**)&aggrP, d_aggr);
    cudaGetSymbolAddress((void**)&zP, d_zA);
    cudaGetSymbolAddress((void**)&tP, d_tB);
    cudaGetSymbolAddress((void**)&statsP, d_stats);
    cudaGetSymbolAddress((void**)&gP, d_g);
    cudaGetSymbolAddress((void**)&g1P, d_g1);
    cudaGetSymbolAddress((void**)&g2P, d_g2);
    cudaGetSymbolAddress((void**)&cminP, d_cminu);
    cudaGetSymbolAddress((void**)&whiP, d_wthi);
    cudaGetSymbolAddress((void**)&wloP, d_wtlo);

    __half* aggrHi = (__half*)aggrP;
    __half* aggrLo = aggrHi + (size_t)NNODES * 256;
    __half* uHi    = (__half*)zP;
    __half* uLo    = uHi + (size_t)NNODES * 128;
    __half* tHi    = (__half*)tP;
    __half* tLo    = tHi + (size_t)NNODES * 256;

    static int smemSet = 0;
    if (!smemSet) {
        cudaFuncSetAttribute(hmma_gemm_kernel,
                             cudaFuncAttributeMaxDynamicSharedMemorySize, 2 * BUFSZ);
        cudaFuncSetAttribute(fused_gemm12_kernel,
                             cudaFuncAttributeMaxDynamicSharedMemorySize, SMEM_FUSED);
        smemSet = 1;
    }

    const int mTiles = (NNODES + 127) / 128;  // 782
    const int SM = 2 * BUFSZ;                 // 75776

    wsplit_kernel<<<1920, 256>>>(merge_W, lin1_W, lin2_W, whiP, wloP);

    fill_u32_kernel<<<(NGRAPHS * CATW + 255) / 256, 256>>>((unsigned*)gP, 0u,
                                                           NGRAPHS * CATW);
    reset_kernel<<<1, 384>>>(statsP, cminP);
    init_kernel<<<SEGBLK, 128>>>(x, hP, membership, gP, cminP);

    for (int i = 0; i < NBLOCKS; i++) {
        aggregate_kernel<<<(NNODES + 15) / 16, 256>>>(hP, nbrs, cminP, aggrHi,
                                                      aggrLo);

        fused_gemm12_kernel<<<mTiles, 256, SMEM_FUSED>>>(
            aggrHi, aggrLo,
            whiP + (size_t)(3 * i + 0) * 32768, wloP + (size_t)(3 * i + 0) * 32768,
            merge_b + i * DIM,
            whiP + (size_t)(3 * i + 1) * 32768, wloP + (size_t)(3 * i + 1) * 32768,
            lin1_b + i * HIDDEN,
            tHi, tLo, NNODES, hP, epsv, i, statsP);

        hmma_gemm_kernel<<<dim3(mTiles, 1), 256, SM>>>(
            tHi, tLo,
            whiP + (size_t)(3 * i + 2) * 32768, wloP + (size_t)(3 * i + 2) * 32768,
            lin2_b + i * DIM, uHi, uLo, NNODES, 256, 128, statsP, cminP);

        bn_apply_kernel<<<SEGBLK, 128>>>(uHi, uLo, statsP, bn_g + i * DIM,
                                         bn_b + i * DIM, 1.0f / NNODES,
                                         membership, gP, (i + 1) * DIM, hP, cminP);
    }

    sgemm_kernel<<<dim3(NGRAPHS / 128, 2), 256>>>(
        gP, dense0_W, dense0_b, g1P, NGRAPHS, CATW, HIDDEN, 1);
    sgemm_kernel<<<dim3(NGRAPHS / 128, 1), 256>>>(
        g1P, dense1_W, dense1_b, g2P, NGRAPHS, HIDDEN, DIM, 1);

    reset_kernel<<<1, 384>>>(statsP, cminP);
    colstats_kernel<<<64, 128>>>(g2P, NGRAPHS, statsP);
    final_kernel<<<NGRAPHS / 8, 256>>>(g2P, statsP, bn0_g, bn0_b, dense2_W,
                                       dense2_b, out);
}